// round 2
// baseline (speedup 1.0000x reference)
#include <cuda_runtime.h>

#define NN 50000
#define DIN 256
#define NC 8
#define NE 1600000

// ---- static device scratch (allocation-free contract) ----
__device__ __align__(16) float g_logb0[NN * NC];
__device__ __align__(16) float g_B[NN * NC];
__device__ __align__(16) float g_agg[NN * NC];
__device__ __align__(16) float g_RA[NE * NC];
__device__ __align__(16) float g_RB[NE * NC];
__device__ int g_src[NE];
__device__ int g_dst[NE];
__device__ int g_rv[NE];
__device__ int g_odd_nonzero;  // !=0 -> indices are int32; ==0 -> int64

__device__ __forceinline__ float frcp(float x) {
    float r;
    asm("rcp.approx.f32 %0, %1;" : "=f"(r) : "f"(x));
    return r;
}

// --- dtype detection: reset flag ---
__global__ void reset_flag_kernel() { g_odd_nonzero = 0; }

// Scan odd 32-bit words of the first 2*NE words of edge_index.
// int64 layout: those are high halves of src values (< 2^31) -> all zero.
// int32 layout: real src/dst index values -> some nonzero (w.p. ~1).
// Reads stay within 2*NE words = the minimum buffer size for either dtype.
__global__ void __launch_bounds__(256) detect_kernel(const int* __restrict__ w) {
    int i = blockIdx.x * 256 + threadIdx.x;  // pair index, i < NE
    int v = 0;
    if (i < NE) v = w[2 * i + 1];
    unsigned any = __ballot_sync(0xffffffffu, v != 0);
    if ((threadIdx.x & 31) == 0 && any) atomicOr(&g_odd_nonzero, 1);
}

// index compaction (int64 or int32 source, selected by runtime flag)
__global__ void __launch_bounds__(256) prep_kernel(const void* __restrict__ ei,
                                                   const void* __restrict__ rv) {
    int e = blockIdx.x * 256 + threadIdx.x;
    if (e >= NE) return;
    if (g_odd_nonzero) {  // int32 inputs
        const int* ei32 = (const int*)ei;
        const int* rv32 = (const int*)rv;
        g_src[e] = ei32[e];
        g_dst[e] = ei32[NE + e];
        g_rv[e] = rv32[e];
    } else {  // int64 inputs
        const long long* ei64 = (const long long*)ei;
        const long long* rv64 = (const long long*)rv;
        g_src[e] = (int)ei64[e];
        g_dst[e] = (int)ei64[NE + e];
        g_rv[e] = (int)rv64[e];
    }
}

// log_b0 = log_softmax(x @ W + b); also B = exp(log_b0), agg init = log_b0.
// One warp per node; lane handles k = lane + 32j.
__global__ void __launch_bounds__(256) transform_kernel(const float* __restrict__ x,
                                                        const float* __restrict__ W,
                                                        const float* __restrict__ bias) {
    __shared__ float sWt[NC][DIN];
    int tid = threadIdx.x;
    for (int i = tid; i < DIN * NC; i += 256) {
        int k = i >> 3, c = i & 7;  // W row-major [DIN, NC]
        sWt[c][k] = W[i];
    }
    __syncthreads();

    int lane = tid & 31;
    int node = blockIdx.x * 8 + (tid >> 5);
    if (node >= NN) return;

    const float* xr = x + node * DIN;
    float xv[8];
#pragma unroll
    for (int j = 0; j < 8; j++) xv[j] = xr[j * 32 + lane];

    float acc[NC];
#pragma unroll
    for (int c = 0; c < NC; c++) {
        float a = 0.f;
#pragma unroll
        for (int j = 0; j < 8; j++) a = fmaf(xv[j], sWt[c][j * 32 + lane], a);
        acc[c] = a;
    }
#pragma unroll
    for (int c = 0; c < NC; c++) {
#pragma unroll
        for (int off = 16; off; off >>= 1)
            acc[c] += __shfl_xor_sync(0xffffffffu, acc[c], off);
    }

    float m = -3.4e38f;
#pragma unroll
    for (int c = 0; c < NC; c++) {
        acc[c] += bias[c];
        m = fmaxf(m, acc[c]);
    }
    float e[NC], S = 0.f;
#pragma unroll
    for (int c = 0; c < NC; c++) {
        e[c] = __expf(acc[c] - m);
        S += e[c];
    }
    float lS = __logf(S);
    float iS = frcp(S);
    if (lane < NC) {
        float lb = acc[lane] - m - lS;
        g_logb0[node * NC + lane] = lb;
        g_agg[node * NC + lane] = lb;
        g_B[node * NC + lane] = e[lane] * iS;
    }
}

// Per-edge message update.
// u[c] = B[src][c] * R_prev[rv][c]           (scale-invariant linear domain)
// q'[c] = 1 + beta * u[c]/U,  beta = e^3-1   (q' in [1, 20.09])
// log_msg[c] = log(q'[c]) - C2,  C2 = log(e^3+7)
// R_next[c] = 1/q'[c]
// agg[dst] += log_msg                        (vector f32 global reduction)
template <bool FIRST, bool LAST, int PREV, int NEXT>
__global__ void __launch_bounds__(256) edge_step_kernel() {
    int e = blockIdx.x * 256 + threadIdx.x;
    if (e >= NE) return;

    int s = __ldg(g_src + e);
    int d = __ldg(g_dst + e);

    float4 b0 = *(const float4*)(g_B + s * NC);
    float4 b1 = *(const float4*)(g_B + s * NC + 4);

    float u[NC];
    if (FIRST) {
        u[0] = b0.x; u[1] = b0.y; u[2] = b0.z; u[3] = b0.w;
        u[4] = b1.x; u[5] = b1.y; u[6] = b1.z; u[7] = b1.w;
    } else {
        const float* __restrict__ Rprev = (PREV == 0) ? g_RA : g_RB;
        int r = __ldg(g_rv + e);
        float4 r0 = *(const float4*)(Rprev + r * NC);
        float4 r1 = *(const float4*)(Rprev + r * NC + 4);
        u[0] = b0.x * r0.x; u[1] = b0.y * r0.y; u[2] = b0.z * r0.z; u[3] = b0.w * r0.w;
        u[4] = b1.x * r1.x; u[5] = b1.y * r1.y; u[6] = b1.z * r1.z; u[7] = b1.w * r1.w;
    }

    float U = ((u[0] + u[1]) + (u[2] + u[3])) + ((u[4] + u[5]) + (u[6] + u[7]));
    const float beta = 19.085536923187668f;  // e^3 - 1
    const float C2 = 3.2990000f;             // log(e^3 + 7)
    float bi = beta * frcp(U);

    float lg[NC], Rn[NC];
#pragma unroll
    for (int c = 0; c < NC; c++) {
        float qp = fmaf(bi, u[c], 1.0f);
        lg[c] = __logf(qp) - C2;
        if (!LAST) Rn[c] = frcp(qp);
    }

    if (!LAST) {
        float* __restrict__ Rnext = (NEXT == 0) ? g_RA : g_RB;
        *(float4*)(Rnext + e * NC) = make_float4(Rn[0], Rn[1], Rn[2], Rn[3]);
        *(float4*)(Rnext + e * NC + 4) = make_float4(Rn[4], Rn[5], Rn[6], Rn[7]);
    }

    float* ap = g_agg + d * NC;
    asm volatile("red.global.add.v4.f32 [%0], {%1,%2,%3,%4};"
                 :: "l"(ap), "f"(lg[0]), "f"(lg[1]), "f"(lg[2]), "f"(lg[3]) : "memory");
    asm volatile("red.global.add.v4.f32 [%0], {%1,%2,%3,%4};"
                 :: "l"(ap + 4), "f"(lg[4]), "f"(lg[5]), "f"(lg[6]), "f"(lg[7]) : "memory");
}

// Node update: log_b = normalize(agg) (agg already includes log_b0).
// Non-last: store B = exp(log_b), reset agg = log_b0. Last: write log_b to out.
template <bool LAST>
__global__ void __launch_bounds__(256) node_kernel(float* __restrict__ out) {
    int n = blockIdx.x * 256 + threadIdx.x;
    if (n >= NN) return;

    float4 a0 = *(const float4*)(g_agg + n * NC);
    float4 a1 = *(const float4*)(g_agg + n * NC + 4);
    float v[NC] = {a0.x, a0.y, a0.z, a0.w, a1.x, a1.y, a1.z, a1.w};

    float m = v[0];
#pragma unroll
    for (int c = 1; c < NC; c++) m = fmaxf(m, v[c]);

    float e[NC], S = 0.f;
#pragma unroll
    for (int c = 0; c < NC; c++) {
        e[c] = __expf(v[c] - m);
        S += e[c];
    }

    if (LAST) {
        float lS = __logf(S);
        *(float4*)(out + n * NC) =
            make_float4(v[0] - m - lS, v[1] - m - lS, v[2] - m - lS, v[3] - m - lS);
        *(float4*)(out + n * NC + 4) =
            make_float4(v[4] - m - lS, v[5] - m - lS, v[6] - m - lS, v[7] - m - lS);
    } else {
        float iS = frcp(S);
        *(float4*)(g_B + n * NC) = make_float4(e[0] * iS, e[1] * iS, e[2] * iS, e[3] * iS);
        *(float4*)(g_B + n * NC + 4) = make_float4(e[4] * iS, e[5] * iS, e[6] * iS, e[7] * iS);
        float4 l0 = *(const float4*)(g_logb0 + n * NC);
        float4 l1 = *(const float4*)(g_logb0 + n * NC + 4);
        *(float4*)(g_agg + n * NC) = l0;
        *(float4*)(g_agg + n * NC + 4) = l1;
    }
}

extern "C" void kernel_launch(void* const* d_in, const int* in_sizes, int n_in,
                              void* d_out, int out_size) {
    const float* x = (const float*)d_in[0];
    const float* W = (const float*)d_in[1];
    const float* bias = (const float*)d_in[2];
    const void* ei = d_in[3];
    const void* rv = d_in[4];
    float* out = (float*)d_out;

    const int EB = (NE + 255) / 256;  // 6250
    const int NB = (NN + 255) / 256;  // 196

    reset_flag_kernel<<<1, 1>>>();
    detect_kernel<<<EB, 256>>>((const int*)ei);
    prep_kernel<<<EB, 256>>>(ei, rv);
    transform_kernel<<<NN / 8, 256>>>(x, W, bias);

    // step 0: uniform initial messages -> gather skipped, write RA
    edge_step_kernel<true, false, 0, 0><<<EB, 256>>>();
    node_kernel<false><<<NB, 256>>>(nullptr);
    // step 1: read RA, write RB
    edge_step_kernel<false, false, 0, 1><<<EB, 256>>>();
    node_kernel<false><<<NB, 256>>>(nullptr);
    // step 2: read RB, write RA
    edge_step_kernel<false, false, 1, 0><<<EB, 256>>>();
    node_kernel<false><<<NB, 256>>>(nullptr);
    // step 3: read RA, write RB
    edge_step_kernel<false, false, 0, 1><<<EB, 256>>>();
    node_kernel<false><<<NB, 256>>>(nullptr);
    // step 4: read RB, skip R write, final output
    edge_step_kernel<false, true, 1, 0><<<EB, 256>>>();
    node_kernel<true><<<NB, 256>>>(out);
}

// round 3
// speedup vs baseline: 1.4365x; 1.4365x over previous
#include <cuda_runtime.h>
#include <cuda_fp16.h>

#define NN 50000
#define DIN 256
#define NC 8
#define NE 1600000

// ---- static device scratch (allocation-free contract) ----
__device__ __align__(16) float g_logb0[NN * NC];
__device__ __align__(16) float g_B[NN * NC];
__device__ __align__(16) float g_agg[NN * NC];
__device__ __align__(16) __half g_RA[NE * NC];   // fp16 reciprocal messages (ping)
__device__ __align__(16) __half g_RB[NE * NC];   // fp16 reciprocal messages (pong)
__device__ int g_src[NE];
__device__ int g_dst[NE];
__device__ int g_rv[NE];
__device__ int g_odd_nonzero;  // !=0 -> indices are int32; ==0 -> int64

__device__ __forceinline__ float frcp(float x) {
    float r;
    asm("rcp.approx.f32 %0, %1;" : "=f"(r) : "f"(x));
    return r;
}

// --- dtype detection ---
__global__ void reset_flag_kernel() { g_odd_nonzero = 0; }

// Sample odd 32-bit words of the first 4096 index pairs.
// int64 layout: high halves of nonneg values < 2^31 -> all zero.
// int32 layout: uniform node ids -> P(all zero) ~ (2e-5)^4096 ~ 0.
__global__ void __launch_bounds__(256) detect_kernel(const int* __restrict__ w) {
    int v = 0;
#pragma unroll
    for (int j = 0; j < 16; j++) {
        int i = threadIdx.x + j * 256;  // pair index < 4096 <= NE
        v |= w[2 * i + 1];
    }
    unsigned any = __ballot_sync(0xffffffffu, v != 0);
    if ((threadIdx.x & 31) == 0 && any) atomicOr(&g_odd_nonzero, 1);
}

// index compaction (int64 or int32 source, selected by runtime flag)
__global__ void __launch_bounds__(256) prep_kernel(const void* __restrict__ ei,
                                                   const void* __restrict__ rv) {
    int e = blockIdx.x * 256 + threadIdx.x;
    if (e >= NE) return;
    if (g_odd_nonzero) {  // int32 inputs
        const int* ei32 = (const int*)ei;
        const int* rv32 = (const int*)rv;
        g_src[e] = ei32[e];
        g_dst[e] = ei32[NE + e];
        g_rv[e] = rv32[e];
    } else {  // int64 inputs
        const long long* ei64 = (const long long*)ei;
        const long long* rv64 = (const long long*)rv;
        g_src[e] = (int)ei64[e];
        g_dst[e] = (int)ei64[NE + e];
        g_rv[e] = (int)rv64[e];
    }
}

// log_b0 = log_softmax(x @ W + b); also B = exp(log_b0), agg init = log_b0.
// One THREAD per node; x streamed through a transposed smem tile (coalesced
// global loads, conflict-free per-thread smem reads), W broadcast from smem.
#define TTB 128
__global__ void __launch_bounds__(TTB) transform_kernel(const float* __restrict__ x,
                                                        const float* __restrict__ W,
                                                        const float* __restrict__ bias) {
    __shared__ float sx[TTB][36];        // 32-k chunk tile, pitch 36 (conflict-free)
    __shared__ float sW[DIN * NC];       // full W, row-major [DIN][NC]
    __shared__ float sb[NC];

    int tid = threadIdx.x;
    for (int i = tid; i < DIN * NC; i += TTB) sW[i] = W[i];
    if (tid < NC) sb[tid] = bias[tid];

    int node0 = blockIdx.x * TTB;
    int n = node0 + tid;

    float acc[NC] = {0.f, 0.f, 0.f, 0.f, 0.f, 0.f, 0.f, 0.f};

#pragma unroll 1
    for (int chunk = 0; chunk < DIN / 32; chunk++) {
        __syncthreads();
        // load tile: rows node0..node0+127, k-cols chunk*32..+32 (8 float4/row)
#pragma unroll
        for (int i = 0; i < 8; i++) {
            int lin = i * TTB + tid;          // 0..1023
            int row = lin >> 3, c4 = lin & 7;
            int nr = node0 + row;
            float4 v = make_float4(0.f, 0.f, 0.f, 0.f);
            if (nr < NN) v = ((const float4*)(x + nr * DIN + chunk * 32))[c4];
            *(float4*)&sx[row][c4 * 4] = v;
        }
        __syncthreads();
#pragma unroll
        for (int k4 = 0; k4 < 8; k4++) {
            float4 xv = *(float4*)&sx[tid][k4 * 4];
            int kg = chunk * 32 + k4 * 4;
            float xs[4] = {xv.x, xv.y, xv.z, xv.w};
#pragma unroll
            for (int j = 0; j < 4; j++) {
                float4 w0 = *(const float4*)&sW[(kg + j) * NC];
                float4 w1 = *(const float4*)&sW[(kg + j) * NC + 4];
                acc[0] = fmaf(xs[j], w0.x, acc[0]);
                acc[1] = fmaf(xs[j], w0.y, acc[1]);
                acc[2] = fmaf(xs[j], w0.z, acc[2]);
                acc[3] = fmaf(xs[j], w0.w, acc[3]);
                acc[4] = fmaf(xs[j], w1.x, acc[4]);
                acc[5] = fmaf(xs[j], w1.y, acc[5]);
                acc[6] = fmaf(xs[j], w1.z, acc[6]);
                acc[7] = fmaf(xs[j], w1.w, acc[7]);
            }
        }
    }

    if (n >= NN) return;

    float m = -3.4e38f;
#pragma unroll
    for (int c = 0; c < NC; c++) {
        acc[c] += sb[c];
        m = fmaxf(m, acc[c]);
    }
    float e[NC], S = 0.f;
#pragma unroll
    for (int c = 0; c < NC; c++) {
        e[c] = __expf(acc[c] - m);
        S += e[c];
    }
    float lS = __logf(S);
    float iS = frcp(S);
    float lb[NC];
#pragma unroll
    for (int c = 0; c < NC; c++) lb[c] = acc[c] - m - lS;

    *(float4*)(g_logb0 + n * NC) = make_float4(lb[0], lb[1], lb[2], lb[3]);
    *(float4*)(g_logb0 + n * NC + 4) = make_float4(lb[4], lb[5], lb[6], lb[7]);
    *(float4*)(g_agg + n * NC) = make_float4(lb[0], lb[1], lb[2], lb[3]);
    *(float4*)(g_agg + n * NC + 4) = make_float4(lb[4], lb[5], lb[6], lb[7]);
    *(float4*)(g_B + n * NC) = make_float4(e[0] * iS, e[1] * iS, e[2] * iS, e[3] * iS);
    *(float4*)(g_B + n * NC + 4) = make_float4(e[4] * iS, e[5] * iS, e[6] * iS, e[7] * iS);
}

// Per-edge message update (fp16 reciprocal-message state).
// u[c] = B[src][c] * R_prev[rv][c]           (scale-invariant linear domain)
// q'[c] = 1 + beta * u[c]/U,  beta = e^3-1   (q' in [1, 20.09])
// log_msg[c] = log(q'[c]) - C2,  C2 = log(e^3+7)  (exact constant normalizer)
// R_next[c] = 1/q'[c]                        (fp16, 16B per edge)
// agg[dst] += log_msg                        (vector f32 global reduction)
template <bool FIRST, bool LAST, int PREV, int NEXT>
__global__ void __launch_bounds__(256) edge_step_kernel() {
    int e = blockIdx.x * 256 + threadIdx.x;
    if (e >= NE) return;

    int s = __ldg(g_src + e);
    int d = __ldg(g_dst + e);

    float4 b0 = *(const float4*)(g_B + s * NC);
    float4 b1 = *(const float4*)(g_B + s * NC + 4);

    float u[NC];
    if (FIRST) {
        u[0] = b0.x; u[1] = b0.y; u[2] = b0.z; u[3] = b0.w;
        u[4] = b1.x; u[5] = b1.y; u[6] = b1.z; u[7] = b1.w;
    } else {
        const __half* __restrict__ Rprev = (PREV == 0) ? g_RA : g_RB;
        int r = __ldg(g_rv + e);
        uint4 rq = *(const uint4*)(Rprev + (size_t)r * NC);
        const __half2* h = (const __half2*)&rq;
        float2 f0 = __half22float2(h[0]);
        float2 f1 = __half22float2(h[1]);
        float2 f2 = __half22float2(h[2]);
        float2 f3 = __half22float2(h[3]);
        u[0] = b0.x * f0.x; u[1] = b0.y * f0.y; u[2] = b0.z * f1.x; u[3] = b0.w * f1.y;
        u[4] = b1.x * f2.x; u[5] = b1.y * f2.y; u[6] = b1.z * f3.x; u[7] = b1.w * f3.y;
    }

    float U = ((u[0] + u[1]) + (u[2] + u[3])) + ((u[4] + u[5]) + (u[6] + u[7]));
    const float beta = 19.085536923187668f;  // e^3 - 1
    const float C2 = 3.2990048f;             // log(e^3 + 7)
    float bi = beta * frcp(U);

    float lg[NC], Rn[NC];
#pragma unroll
    for (int c = 0; c < NC; c++) {
        float qp = fmaf(bi, u[c], 1.0f);
        lg[c] = __logf(qp) - C2;
        if (!LAST) Rn[c] = frcp(qp);
    }

    if (!LAST) {
        __half* __restrict__ Rnext = (NEXT == 0) ? g_RA : g_RB;
        uint4 out;
        __half2* oh = (__half2*)&out;
        oh[0] = __floats2half2_rn(Rn[0], Rn[1]);
        oh[1] = __floats2half2_rn(Rn[2], Rn[3]);
        oh[2] = __floats2half2_rn(Rn[4], Rn[5]);
        oh[3] = __floats2half2_rn(Rn[6], Rn[7]);
        *(uint4*)(Rnext + (size_t)e * NC) = out;
    }

    float* ap = g_agg + d * NC;
    asm volatile("red.global.add.v4.f32 [%0], {%1,%2,%3,%4};"
                 :: "l"(ap), "f"(lg[0]), "f"(lg[1]), "f"(lg[2]), "f"(lg[3]) : "memory");
    asm volatile("red.global.add.v4.f32 [%0], {%1,%2,%3,%4};"
                 :: "l"(ap + 4), "f"(lg[4]), "f"(lg[5]), "f"(lg[6]), "f"(lg[7]) : "memory");
}

// Node update: log_b = normalize(agg) (agg already includes log_b0).
// Non-last: store B = exp(log_b), reset agg = log_b0. Last: write log_b to out.
template <bool LAST>
__global__ void __launch_bounds__(256) node_kernel(float* __restrict__ out) {
    int n = blockIdx.x * 256 + threadIdx.x;
    if (n >= NN) return;

    float4 a0 = *(const float4*)(g_agg + n * NC);
    float4 a1 = *(const float4*)(g_agg + n * NC + 4);
    float v[NC] = {a0.x, a0.y, a0.z, a0.w, a1.x, a1.y, a1.z, a1.w};

    float m = v[0];
#pragma unroll
    for (int c = 1; c < NC; c++) m = fmaxf(m, v[c]);

    float e[NC], S = 0.f;
#pragma unroll
    for (int c = 0; c < NC; c++) {
        e[c] = __expf(v[c] - m);
        S += e[c];
    }

    if (LAST) {
        float lS = __logf(S);
        *(float4*)(out + n * NC) =
            make_float4(v[0] - m - lS, v[1] - m - lS, v[2] - m - lS, v[3] - m - lS);
        *(float4*)(out + n * NC + 4) =
            make_float4(v[4] - m - lS, v[5] - m - lS, v[6] - m - lS, v[7] - m - lS);
    } else {
        float iS = frcp(S);
        *(float4*)(g_B + n * NC) = make_float4(e[0] * iS, e[1] * iS, e[2] * iS, e[3] * iS);
        *(float4*)(g_B + n * NC + 4) = make_float4(e[4] * iS, e[5] * iS, e[6] * iS, e[7] * iS);
        float4 l0 = *(const float4*)(g_logb0 + n * NC);
        float4 l1 = *(const float4*)(g_logb0 + n * NC + 4);
        *(float4*)(g_agg + n * NC) = l0;
        *(float4*)(g_agg + n * NC + 4) = l1;
    }
}

extern "C" void kernel_launch(void* const* d_in, const int* in_sizes, int n_in,
                              void* d_out, int out_size) {
    const float* x = (const float*)d_in[0];
    const float* W = (const float*)d_in[1];
    const float* bias = (const float*)d_in[2];
    const void* ei = d_in[3];
    const void* rv = d_in[4];
    float* out = (float*)d_out;

    const int EB = (NE + 255) / 256;   // 6250
    const int NB = (NN + 255) / 256;   // 196
    const int TBK = (NN + TTB - 1) / TTB;  // 391

    reset_flag_kernel<<<1, 1>>>();
    detect_kernel<<<1, 256>>>((const int*)ei);
    prep_kernel<<<EB, 256>>>(ei, rv);
    transform_kernel<<<TBK, TTB>>>(x, W, bias);

    // step 0: uniform initial messages -> gather skipped, write RA
    edge_step_kernel<true, false, 0, 0><<<EB, 256>>>();
    node_kernel<false><<<NB, 256>>>(nullptr);
    // step 1: read RA, write RB
    edge_step_kernel<false, false, 0, 1><<<EB, 256>>>();
    node_kernel<false><<<NB, 256>>>(nullptr);
    // step 2: read RB, write RA
    edge_step_kernel<false, false, 1, 0><<<EB, 256>>>();
    node_kernel<false><<<NB, 256>>>(nullptr);
    // step 3: read RA, write RB
    edge_step_kernel<false, false, 0, 1><<<EB, 256>>>();
    node_kernel<false><<<NB, 256>>>(nullptr);
    // step 4: read RB, skip R write, final output
    edge_step_kernel<false, true, 1, 0><<<EB, 256>>>();
    node_kernel<true><<<NB, 256>>>(out);
}